// round 11
// baseline (speedup 1.0000x reference)
#include <cuda_runtime.h>

#define BATCH 4
#define CI    32
#define CO    32
#define NN    64
#define MM    32
#define VV    32768      // 32^3
#define NSH   16
#define NL    9

// -------- static scratch (exonerated; ~102 MB) --------
static __device__ float2 hd_b2[BATCH*CI*NN*MM*MM];   // 67 MB  [bc, d, ph*32+pw]
static __device__ float2 hd_b3[BATCH*CI*MM*MM*MM];   // 33 MB  Xb / Xrec
static __device__ float2 hd_coef[BATCH*CI*NSH*NL];
static __device__ float2 hd_mixg[BATCH*CO*NSH*NL];
static __device__ float2 hd_F[NN*MM];                // F[n][p] = e^{-i pi (p-16) n / 32}
static __device__ float2 hd_G[MM*NN];                // G[p][n] = e^{+i pi (p-16) n / 32} / 64
static __device__ float  hd_Y[NL*VV];
static __device__ int    hd_sh[VV];
static __device__ float  hd_cnt[NSH];

// ---------------- init ----------------
static __global__ void hd_tables() {
    int t = threadIdx.x;
    for (int idx = t; idx < NN*MM; idx += blockDim.x) {
        int n = idx / MM, p = idx % MM;
        float a = -(float)((p - 16) * n) / 32.0f;
        float s, c; sincospif(a, &s, &c);
        hd_F[idx] = make_float2(c, s);
    }
    for (int idx = t; idx < MM*NN; idx += blockDim.x) {
        int p = idx / NN, n = idx % NN;
        float a = (float)((p - 16) * n) / 32.0f;
        float s, c; sincospif(a, &s, &c);
        hd_G[idx] = make_float2(c * (1.0f/64.0f), s * (1.0f/64.0f));
    }
}

static __global__ void hd_basis() {
    int v = blockIdx.x * blockDim.x + threadIdx.x;
    if (v >= VV) return;
    int p = v >> 10, q = (v >> 5) & 31, w = v & 31;
    int kx = p - 16, ky = q - 16, kz = w - 16;
    int q2 = kx*kx + ky*ky + kz*kz;
    float Yv[NL];
    int shell;
    if (q2 == 0) {
        Yv[0] = 0.282095f;
        #pragma unroll
        for (int l = 1; l < NL; l++) Yv[l] = 0.0f;
        shell = 0;
    } else {
        float r    = __fsqrt_rn((float)q2);
        float rmax = __fsqrt_rn(768.0f);
        float ux = __fdiv_rn((float)kx, r);
        float uy = __fdiv_rn((float)ky, r);
        float uz = __fdiv_rn((float)kz, r);
        Yv[0] = 0.282095f;
        Yv[1] = 0.488603f * uy;
        Yv[2] = 0.488603f * uz;
        Yv[3] = 0.488603f * ux;
        Yv[4] = 1.092548f * ux * uy;
        Yv[5] = 1.092548f * uy * uz;
        Yv[6] = 0.315392f * (3.0f * uz * uz - 1.0f);
        Yv[7] = 1.092548f * ux * uz;
        Yv[8] = 0.546274f * (ux * ux - uy * uy);
        float val = __fmul_rn(__fdiv_rn(r, rmax), 16.0f);
        shell = (int)val; if (shell > 15) shell = 15;
    }
    hd_sh[v] = shell;
    #pragma unroll
    for (int l = 0; l < NL; l++) hd_Y[l*VV + v] = Yv[l];
}

static __global__ void hd_counts() {
    __shared__ int hist[NSH];
    int t = threadIdx.x;
    if (t < NSH) hist[t] = 0;
    __syncthreads();
    for (int v = t; v < VV; v += blockDim.x) atomicAdd(&hist[hd_sh[v]], 1);
    __syncthreads();
    if (t < NSH) hd_cnt[t] = (float)max(hist[t], 1);
}

// ---------------- forward W+H: block per (b,c,d) slab ----------------
static __global__ void hd_f12(const float* __restrict__ x, long xcap) {
    __shared__ float  xs[64*64];
    __shared__ float2 mid[64*32];
    int t = threadIdx.x;
    long base = (long)blockIdx.x * 4096;
    for (int i = t; i < 4096; i += 256) {
        long gi = base + i;
        xs[i] = (gi < xcap) ? x[gi] : 0.0f;
    }
    __syncthreads();
    {   // W axis
        int pw = t & 31, hg = t >> 5;
        float2 acc[8];
        #pragma unroll
        for (int k = 0; k < 8; k++) acc[k] = make_float2(0.f, 0.f);
        #pragma unroll 4
        for (int w = 0; w < 64; w++) {
            float2 f = hd_F[w*32 + pw];
            #pragma unroll
            for (int k = 0; k < 8; k++) {
                float xv = xs[(hg + 8*k)*64 + w];
                acc[k].x += xv * f.x;
                acc[k].y += xv * f.y;
            }
        }
        #pragma unroll
        for (int k = 0; k < 8; k++) mid[(hg + 8*k)*32 + pw] = acc[k];
    }
    __syncthreads();
    {   // H axis
        int pw = t & 31, pg = t >> 5;
        float2 acc[4];
        #pragma unroll
        for (int k = 0; k < 4; k++) acc[k] = make_float2(0.f, 0.f);
        #pragma unroll 4
        for (int h = 0; h < 64; h++) {
            float2 m = mid[h*32 + pw];
            #pragma unroll
            for (int k = 0; k < 4; k++) {
                float2 f = hd_F[h*32 + (pg + 8*k)];
                acc[k].x += m.x * f.x - m.y * f.y;
                acc[k].y += m.x * f.y + m.y * f.x;
            }
        }
        long obase = (long)blockIdx.x * 1024;
        #pragma unroll
        for (int k = 0; k < 4; k++)
            hd_b2[obase + (pg + 8*k)*32 + pw] = acc[k];
    }
}

// ---------------- forward D: hd_b2 -> hd_b3 ----------------
static __global__ void hd_s3f() {
    __shared__ float2 ins[64*32];
    __shared__ float2 Fs[NN*MM];
    int t = threadIdx.x;
    int bc = blockIdx.x >> 5, jc = blockIdx.x & 31;
    long base = (long)bc * 65536 + jc * 32;
    for (int i = t; i < 2048; i += 256) {
        int d = i >> 5, jj = i & 31;
        ins[i] = hd_b2[base + (long)d * 1024 + jj];
    }
    for (int i = t; i < NN*MM; i += 256) Fs[i] = hd_F[i];
    __syncthreads();
    int jj = t & 31, pg = t >> 5;
    float2 acc[4];
    #pragma unroll
    for (int k = 0; k < 4; k++) acc[k] = make_float2(0.f, 0.f);
    #pragma unroll 4
    for (int d = 0; d < 64; d++) {
        float2 xv = ins[d*32 + jj];
        #pragma unroll
        for (int k = 0; k < 4; k++) {
            float2 f = Fs[d*32 + (pg + 8*k)];
            acc[k].x += xv.x * f.x - xv.y * f.y;
            acc[k].y += xv.x * f.y + xv.y * f.x;
        }
    }
    long obase = (long)bc * 32768 + jc * 32;
    #pragma unroll
    for (int k = 0; k < 4; k++)
        hd_b3[obase + (long)(pg + 8*k) * 1024 + jj] = acc[k];
}

// ---------------- projection ----------------
static __global__ void hd_proj() {
    int bi = blockIdx.x >> 4, s = blockIdx.x & 15;
    int t = threadIdx.x;
    long base = (long)bi * VV;
    float2 acc[NL];
    #pragma unroll
    for (int l = 0; l < NL; l++) acc[l] = make_float2(0.f, 0.f);
    for (int v = t; v < VV; v += 256) {
        if (hd_sh[v] == s) {
            float2 X = hd_b3[base + v];
            #pragma unroll
            for (int l = 0; l < NL; l++) {
                float y = hd_Y[l*VV + v];
                acc[l].x += y * X.x;
                acc[l].y += y * X.y;
            }
        }
    }
    __shared__ float2 red[256];
    float inv = 1.0f / hd_cnt[s];
    for (int l = 0; l < NL; l++) {
        red[t] = acc[l];
        __syncthreads();
        for (int off = 128; off > 0; off >>= 1) {
            if (t < off) { red[t].x += red[t+off].x; red[t].y += red[t+off].y; }
            __syncthreads();
        }
        if (t == 0)
            hd_coef[(bi*NSH + s)*NL + l] = make_float2(red[0].x * inv, red[0].y * inv);
        __syncthreads();
    }
}

// ---------------- channel mix ----------------
static __global__ void hd_mix(const float* __restrict__ Wr,
                              const float* __restrict__ Wi, long wcap) {
    int gid = blockIdx.x * blockDim.x + threadIdx.x;
    if (gid >= BATCH*CO*NSH*NL) return;
    int l = gid % NL;
    int s = (gid / NL) % NSH;
    int o = (gid / (NL*NSH)) % CO;
    int b = gid / (NL*NSH*CO);
    float ar = 0.f, ai = 0.f;
    for (int i = 0; i < CI; i++) {
        float2 c = hd_coef[((b*CI + i)*NSH + s)*NL + l];
        long wi = ((long)(i*CO + o)*NSH + s)*NL + l;
        float wr  = (wi < wcap) ? Wr[wi] : 0.0f;
        float wim = (wi < wcap) ? Wi[wi] : 0.0f;
        ar += c.x * wr - c.y * wim;
        ai += c.x * wim + c.y * wr;
    }
    hd_mixg[gid] = make_float2(ar, ai);
}

// ---------------- reconstruction -> hd_b3 ----------------
static __global__ void hd_recon() {
    __shared__ float2 mix_s[NSH*NL];
    int bo = blockIdx.x >> 7, chunk = blockIdx.x & 127;
    int t = threadIdx.x;
    if (t < NSH*NL) mix_s[t] = hd_mixg[bo*NSH*NL + t];
    __syncthreads();
    int v = chunk * 256 + t;
    int s = hd_sh[v];
    float ar = 0.f, ai = 0.f;
    #pragma unroll
    for (int l = 0; l < NL; l++) {
        float y = hd_Y[l*VV + v];
        float2 m = mix_s[s*NL + l];
        ar += y * m.x;
        ai += y * m.y;
    }
    hd_b3[(long)bo * VV + v] = make_float2(ar, ai);
}

// ---------------- inverse D (32->64): hd_b3 -> hd_b2 ----------------
static __global__ void hd_invD() {
    __shared__ float2 ins[32*32];
    __shared__ float2 Gs[MM*NN];
    int t = threadIdx.x;
    int bo = blockIdx.x >> 5, jc = blockIdx.x & 31;
    long base = (long)bo * 32768 + jc * 32;
    for (int i = t; i < 1024; i += 256) {
        int pd = i >> 5, jj = i & 31;
        ins[i] = hd_b3[base + (long)pd * 1024 + jj];
    }
    for (int i = t; i < MM*NN; i += 256) Gs[i] = hd_G[i];
    __syncthreads();
    int jj = t & 31, dg = t >> 5;
    float2 acc[8];
    #pragma unroll
    for (int k = 0; k < 8; k++) acc[k] = make_float2(0.f, 0.f);
    #pragma unroll 4
    for (int pd = 0; pd < 32; pd++) {
        float2 xv = ins[pd*32 + jj];
        #pragma unroll
        for (int k = 0; k < 8; k++) {
            float2 g = Gs[pd*64 + (dg + 8*k)];
            acc[k].x += xv.x * g.x - xv.y * g.y;
            acc[k].y += xv.x * g.y + xv.y * g.x;
        }
    }
    long obase = (long)bo * 65536 + jc * 32;
    #pragma unroll
    for (int k = 0; k < 8; k++)
        hd_b2[obase + (long)(dg + 8*k) * 1024 + jj] = acc[k];
}

// ---------------- inverse H+W: hd_b2 -> out (adaptive real/interleaved) -------
static __global__ void hd_invHW(float* __restrict__ outf, long fcap, int interleaved) {
    __shared__ float2 ins[32*32];
    __shared__ float2 Gs[MM*NN];
    __shared__ float2 mid[64*32];
    int t = threadIdx.x;
    long base = (long)blockIdx.x * 1024;
    for (int i = t; i < 1024; i += 256) ins[i] = hd_b2[base + i];
    for (int i = t; i < MM*NN; i += 256) Gs[i] = hd_G[i];
    __syncthreads();
    {   // H axis 32->64
        int pw = t & 31, hg = t >> 5;
        float2 acc[8];
        #pragma unroll
        for (int k = 0; k < 8; k++) acc[k] = make_float2(0.f, 0.f);
        #pragma unroll 4
        for (int ph = 0; ph < 32; ph++) {
            float2 xv = ins[ph*32 + pw];
            #pragma unroll
            for (int k = 0; k < 8; k++) {
                float2 g = Gs[ph*64 + (hg + 8*k)];
                acc[k].x += xv.x * g.x - xv.y * g.y;
                acc[k].y += xv.x * g.y + xv.y * g.x;
            }
        }
        #pragma unroll
        for (int k = 0; k < 8; k++) mid[(hg + 8*k)*32 + pw] = acc[k];
    }
    __syncthreads();
    {   // W axis 32->64
        int w = t & 63, hg = t >> 6;
        float2 acc[16];
        #pragma unroll
        for (int k = 0; k < 16; k++) acc[k] = make_float2(0.f, 0.f);
        #pragma unroll 2
        for (int pw = 0; pw < 32; pw++) {
            float2 g = Gs[pw*64 + w];
            #pragma unroll
            for (int k = 0; k < 16; k++) {
                float2 m = mid[(hg + 4*k)*32 + pw];
                acc[k].x += m.x * g.x - m.y * g.y;
                acc[k].y += m.x * g.y + m.y * g.x;
            }
        }
        long obase = (long)blockIdx.x * 4096;
        if (interleaved) {
            #pragma unroll
            for (int k = 0; k < 16; k++) {
                long fi = (obase + (hg + 4*k)*64 + w) * 2;
                if (fi + 1 < fcap) { outf[fi] = acc[k].x; outf[fi+1] = acc[k].y; }
            }
        } else {
            #pragma unroll
            for (int k = 0; k < 16; k++) {
                long fi = obase + (hg + 4*k)*64 + w;
                if (fi < fcap) outf[fi] = acc[k].x;      // real part only
            }
        }
    }
}

extern "C" void kernel_launch(void* const* d_in, const int* in_sizes, int n_in,
                              void* d_out, int out_size) {
    const float* x  = nullptr;  long xcap = 0;
    const float* Wsmall[2] = {nullptr, nullptr};
    long wcap = 0;
    int nsmall = 0;
    for (int i = 0; i < n_in; i++) {
        if (in_sizes[i] > 1000000) {
            x = (const float*)d_in[i];
            xcap = (long)in_sizes[i];
        } else if (nsmall < 2) {
            if (nsmall == 0) wcap = (long)in_sizes[i];
            Wsmall[nsmall++] = (const float*)d_in[i];
        }
    }
    if (!x || nsmall < 2) return;
    const float* Wr = Wsmall[0];
    const float* Wi = Wsmall[1];

    // Guaranteed float capacity of d_out under both interpretations of out_size:
    //   elements: cap = out_size floats;  bytes: cap = out_size/4 floats.
    // 33.5M  -> elements, real-only   (134 MB buffer)
    // 67.1M  -> elements, interleaved (268 MB buffer)
    // 134.2M -> bytes,    real-only   (134 MB buffer)
    // 268.4M -> bytes,    interleaved (268 MB buffer)
    long S = (long)out_size;
    long fcap;        // floats we may legally touch
    int  interleaved; // write re,im pairs vs real only
    if (S >= 200000000)      { fcap = S / 4; interleaved = 1; }
    else if (S >= 100000000) { fcap = S / 4; interleaved = 0; }
    else if (S >= 50000000)  { fcap = S;     interleaved = 1; }
    else                     { fcap = S;     interleaved = 0; }
    float* outf = (float*)d_out;

    hd_tables<<<1, 256>>>();
    hd_basis<<<VV/256, 256>>>();
    hd_counts<<<1, 256>>>();

    hd_f12<<<BATCH*CI*NN, 256>>>(x, xcap);    // 8192 blocks
    hd_s3f<<<BATCH*CI*32, 256>>>();           // 4096

    hd_proj<<<BATCH*CI*NSH, 256>>>();         // 2048
    hd_mix<<<(BATCH*CO*NSH*NL + 255)/256, 256>>>(Wr, Wi, wcap);
    hd_recon<<<BATCH*CO*128, 256>>>();        // 16384

    hd_invD<<<BATCH*CO*32, 256>>>();          // 4096
    hd_invHW<<<BATCH*CO*NN, 256>>>(outf, fcap, interleaved);   // 8192
}

// round 14
// speedup vs baseline: 1.5808x; 1.5808x over previous
#include <cuda_runtime.h>

#define BATCH 4
#define CI    32
#define CO    32
#define NN    64
#define MM    32
#define VV    32768      // 32^3
#define NSH   16
#define NL    9
#define NBLK  128        // VV/256 voxel blocks for the sort

// -------- static scratch --------
static __device__ float2 hd_b2[BATCH*CI*NN*MM*MM];   // 67 MB  [bc*64+d][1024]
static __device__ float2 hd_b3[BATCH*CI*MM*MM*MM];   // 33 MB  Xb / Xrec
static __device__ float2 hd_coef[BATCH*CI*NSH*NL];
static __device__ float2 hd_mixg[BATCH*CO*NSH*NL];
static __device__ float2 hd_F[NN*MM];                // F[n][p] = e^{-i pi (p-16) n / 32}
static __device__ float2 hd_G[MM*NN];                // G[p][n] = e^{+i pi (p-16) n / 32} / 64
static __device__ float  hd_Y[NL*VV];
static __device__ int    hd_sh[VV];
// sort structures
static __device__ int    hd_bcnt[NBLK*NSH];
static __device__ int    hd_boff[NBLK*NSH];
static __device__ int    hd_shoff[NSH+1];
static __device__ int    hd_vidx[VV];
static __device__ float  hd_Ys[NL*VV];               // Y in shell-sorted order

// ---------------- init: twiddles ----------------
static __global__ void hd_tables() {
    int t = threadIdx.x;
    for (int idx = t; idx < NN*MM; idx += blockDim.x) {
        int n = idx / MM, p = idx % MM;
        float a = -(float)((p - 16) * n) / 32.0f;
        float s, c; sincospif(a, &s, &c);
        hd_F[idx] = make_float2(c, s);
    }
    for (int idx = t; idx < MM*NN; idx += blockDim.x) {
        int p = idx / NN, n = idx % NN;
        float a = (float)((p - 16) * n) / 32.0f;
        float s, c; sincospif(a, &s, &c);
        hd_G[idx] = make_float2(c * (1.0f/64.0f), s * (1.0f/64.0f));
    }
}

// ---------------- init: shell + SH basis ----------------
static __global__ void hd_basis() {
    int v = blockIdx.x * blockDim.x + threadIdx.x;
    if (v >= VV) return;
    int p = v >> 10, q = (v >> 5) & 31, w = v & 31;
    int kx = p - 16, ky = q - 16, kz = w - 16;
    int q2 = kx*kx + ky*ky + kz*kz;
    float Yv[NL];
    int shell;
    if (q2 == 0) {
        Yv[0] = 0.282095f;
        #pragma unroll
        for (int l = 1; l < NL; l++) Yv[l] = 0.0f;
        shell = 0;
    } else {
        float r    = __fsqrt_rn((float)q2);
        float rmax = __fsqrt_rn(768.0f);
        float ux = __fdiv_rn((float)kx, r);
        float uy = __fdiv_rn((float)ky, r);
        float uz = __fdiv_rn((float)kz, r);
        Yv[0] = 0.282095f;
        Yv[1] = 0.488603f * uy;
        Yv[2] = 0.488603f * uz;
        Yv[3] = 0.488603f * ux;
        Yv[4] = 1.092548f * ux * uy;
        Yv[5] = 1.092548f * uy * uz;
        Yv[6] = 0.315392f * (3.0f * uz * uz - 1.0f);
        Yv[7] = 1.092548f * ux * uz;
        Yv[8] = 0.546274f * (ux * ux - uy * uy);
        float val = __fmul_rn(__fdiv_rn(r, rmax), 16.0f);
        shell = (int)val; if (shell > 15) shell = 15;
    }
    hd_sh[v] = shell;
    #pragma unroll
    for (int l = 0; l < NL; l++) hd_Y[l*VV + v] = Yv[l];
}

// ---------------- sort: per-block shell counts ----------------
static __global__ void hd_blkcnt() {        // grid NBLK, block 256
    __shared__ int cnt[NSH];
    int t = threadIdx.x;
    if (t < NSH) cnt[t] = 0;
    __syncthreads();
    atomicAdd(&cnt[hd_sh[blockIdx.x*256 + t]], 1);
    __syncthreads();
    if (t < NSH) hd_bcnt[blockIdx.x*NSH + t] = cnt[t];
}

// ---------------- sort: offsets (1 block, 32 threads) ----------------
static __global__ void hd_scan() {
    __shared__ int tot[NSH];
    int s = threadIdx.x;
    if (s < NSH) {
        int c = 0;
        for (int b = 0; b < NBLK; b++) c += hd_bcnt[b*NSH + s];
        tot[s] = c;
    }
    __syncthreads();
    if (s == 0) {
        int run = 0;
        for (int i = 0; i < NSH; i++) { hd_shoff[i] = run; run += tot[i]; }
        hd_shoff[NSH] = run;
    }
    __syncthreads();
    if (s < NSH) {
        int run = hd_shoff[s];
        for (int b = 0; b < NBLK; b++) { hd_boff[b*NSH + s] = run; run += hd_bcnt[b*NSH + s]; }
    }
}

// ---------------- sort: deterministic scatter ----------------
static __global__ void hd_scatter() {       // grid NBLK, block 256
    __shared__ int pos[256];
    int t = threadIdx.x;
    int v0 = blockIdx.x * 256;
    if (t == 0) {
        int local[NSH];
        #pragma unroll
        for (int s = 0; s < NSH; s++) local[s] = hd_boff[blockIdx.x*NSH + s];
        for (int i = 0; i < 256; i++) { int s = hd_sh[v0 + i]; pos[i] = local[s]++; }
    }
    __syncthreads();
    hd_vidx[pos[t]] = v0 + t;
}

// ---------------- sort: permute Y into shell order ----------------
static __global__ void hd_perm() {          // grid NBLK, block 256
    int j = blockIdx.x * 256 + threadIdx.x;
    int v = hd_vidx[j];
    #pragma unroll
    for (int l = 0; l < NL; l++) hd_Ys[l*VV + j] = hd_Y[l*VV + v];
}

// ---------------- forward W+H (radix-2): block per (b,c,d) slab ----------------
static __global__ void hd_f12(const float* __restrict__ x, long xcap) {
    __shared__ float  xs[64*64];
    __shared__ float2 mid[64*32];
    int t = threadIdx.x;
    long base = (long)blockIdx.x * 4096;
    for (int i = t; i < 4096; i += 256) {
        long gi = base + i;
        xs[i] = (gi < xcap) ? x[gi] : 0.0f;
    }
    __syncthreads();
    // butterfly W: xs[h][w'] = x[w']+x[w'+32], xs[h][w'+32] = x[w']-x[w'+32]
    for (int i = t; i < 2048; i += 256) {
        int h = i >> 5, w = i & 31;
        float a = xs[h*64 + w], b = xs[h*64 + w + 32];
        xs[h*64 + w] = a + b;
        xs[h*64 + w + 32] = a - b;
    }
    __syncthreads();
    {   // stage A (W axis, 32-term): parity of pw selects u/v rows
        int pw = t & 31, hg = t >> 5;
        int off = (pw & 1) ? 32 : 0;
        float2 acc[8];
        #pragma unroll
        for (int k = 0; k < 8; k++) acc[k] = make_float2(0.f, 0.f);
        #pragma unroll 4
        for (int w = 0; w < 32; w++) {
            float2 f = hd_F[w*32 + pw];
            #pragma unroll
            for (int k = 0; k < 8; k++) {
                float xv = xs[(hg + 8*k)*64 + off + w];
                acc[k].x += xv * f.x;
                acc[k].y += xv * f.y;
            }
        }
        #pragma unroll
        for (int k = 0; k < 8; k++) mid[(hg + 8*k)*32 + pw] = acc[k];
    }
    __syncthreads();
    // butterfly H on mid (complex)
    for (int i = t; i < 1024; i += 256) {
        int h = i >> 5, pw = i & 31;
        float2 a = mid[h*32 + pw], b = mid[(h + 32)*32 + pw];
        mid[h*32 + pw]       = make_float2(a.x + b.x, a.y + b.y);
        mid[(h + 32)*32 + pw] = make_float2(a.x - b.x, a.y - b.y);
    }
    __syncthreads();
    {   // stage B (H axis, 32-term): parity of pg (= parity of ph)
        int pw = t & 31, pg = t >> 5;
        int off = (pg & 1) ? 32 : 0;
        float2 acc[4];
        #pragma unroll
        for (int k = 0; k < 4; k++) acc[k] = make_float2(0.f, 0.f);
        #pragma unroll 4
        for (int h = 0; h < 32; h++) {
            float2 m = mid[(off + h)*32 + pw];
            #pragma unroll
            for (int k = 0; k < 4; k++) {
                float2 f = hd_F[h*32 + (pg + 8*k)];
                acc[k].x += m.x * f.x - m.y * f.y;
                acc[k].y += m.x * f.y + m.y * f.x;
            }
        }
        long obase = (long)blockIdx.x * 1024;
        #pragma unroll
        for (int k = 0; k < 4; k++)
            hd_b2[obase + (pg + 8*k)*32 + pw] = acc[k];
    }
}

// ---------------- forward D (radix-2): hd_b2 -> hd_b3 ----------------
static __global__ void hd_s3f() {
    __shared__ float2 ins[64*32];
    __shared__ float2 Fs[MM*MM];    // rows w<32 of F
    int t = threadIdx.x;
    int bc = blockIdx.x >> 5, jc = blockIdx.x & 31;
    long base = (long)bc * 65536 + jc * 32;
    for (int i = t; i < 2048; i += 256) {
        int d = i >> 5, jj = i & 31;
        ins[i] = hd_b2[base + (long)d * 1024 + jj];
    }
    for (int i = t; i < MM*MM; i += 256) Fs[i] = hd_F[i];
    __syncthreads();
    // butterfly D
    for (int i = t; i < 1024; i += 256) {
        int d = i >> 5, jj = i & 31;
        float2 a = ins[d*32 + jj], b = ins[(d + 32)*32 + jj];
        ins[d*32 + jj]        = make_float2(a.x + b.x, a.y + b.y);
        ins[(d + 32)*32 + jj] = make_float2(a.x - b.x, a.y - b.y);
    }
    __syncthreads();
    int jj = t & 31, pg = t >> 5;
    int off = (pg & 1) ? 32 : 0;
    float2 acc[4];
    #pragma unroll
    for (int k = 0; k < 4; k++) acc[k] = make_float2(0.f, 0.f);
    #pragma unroll 4
    for (int d = 0; d < 32; d++) {
        float2 xv = ins[(off + d)*32 + jj];
        #pragma unroll
        for (int k = 0; k < 4; k++) {
            float2 f = Fs[d*32 + (pg + 8*k)];
            acc[k].x += xv.x * f.x - xv.y * f.y;
            acc[k].y += xv.x * f.y + xv.y * f.x;
        }
    }
    long obase = (long)bc * 32768 + jc * 32;
    #pragma unroll
    for (int k = 0; k < 4; k++)
        hd_b3[obase + (long)(pg + 8*k) * 1024 + jj] = acc[k];
}

// ---------------- projection (shell-sorted) ----------------
static __global__ void hd_proj() {
    int bi = blockIdx.x >> 4, s = blockIdx.x & 15;
    int t = threadIdx.x;
    int st = hd_shoff[s], en = hd_shoff[s+1];
    long base = (long)bi * VV;
    float2 acc[NL];
    #pragma unroll
    for (int l = 0; l < NL; l++) acc[l] = make_float2(0.f, 0.f);
    for (int j = st + t; j < en; j += 256) {
        int v = hd_vidx[j];
        float2 X = hd_b3[base + v];
        #pragma unroll
        for (int l = 0; l < NL; l++) {
            float y = hd_Ys[l*VV + j];
            acc[l].x += y * X.x;
            acc[l].y += y * X.y;
        }
    }
    __shared__ float2 red[256];
    int n = en - st; if (n < 1) n = 1;
    float inv = 1.0f / (float)n;
    for (int l = 0; l < NL; l++) {
        red[t] = acc[l];
        __syncthreads();
        for (int off = 128; off > 0; off >>= 1) {
            if (t < off) { red[t].x += red[t+off].x; red[t].y += red[t+off].y; }
            __syncthreads();
        }
        if (t == 0)
            hd_coef[(bi*NSH + s)*NL + l] = make_float2(red[0].x * inv, red[0].y * inv);
        __syncthreads();
    }
}

// ---------------- channel mix ----------------
static __global__ void hd_mix(const float* __restrict__ Wr,
                              const float* __restrict__ Wi, long wcap) {
    int gid = blockIdx.x * blockDim.x + threadIdx.x;
    if (gid >= BATCH*CO*NSH*NL) return;
    int l = gid % NL;
    int s = (gid / NL) % NSH;
    int o = (gid / (NL*NSH)) % CO;
    int b = gid / (NL*NSH*CO);
    float ar = 0.f, ai = 0.f;
    for (int i = 0; i < CI; i++) {
        float2 c = hd_coef[((b*CI + i)*NSH + s)*NL + l];
        long wi = ((long)(i*CO + o)*NSH + s)*NL + l;
        float wr  = (wi < wcap) ? Wr[wi] : 0.0f;
        float wim = (wi < wcap) ? Wi[wi] : 0.0f;
        ar += c.x * wr - c.y * wim;
        ai += c.x * wim + c.y * wr;
    }
    hd_mixg[gid] = make_float2(ar, ai);
}

// ---------------- reconstruction -> hd_b3 ----------------
static __global__ void hd_recon() {
    __shared__ float2 mix_s[NSH*NL];
    int bo = blockIdx.x >> 7, chunk = blockIdx.x & 127;
    int t = threadIdx.x;
    if (t < NSH*NL) mix_s[t] = hd_mixg[bo*NSH*NL + t];
    __syncthreads();
    int v = chunk * 256 + t;
    int s = hd_sh[v];
    float ar = 0.f, ai = 0.f;
    #pragma unroll
    for (int l = 0; l < NL; l++) {
        float y = hd_Y[l*VV + v];
        float2 m = mix_s[s*NL + l];
        ar += y * m.x;
        ai += y * m.y;
    }
    hd_b3[(long)bo * VV + v] = make_float2(ar, ai);
}

// ---------------- inverse D (radix-2, 32->64): hd_b3 -> hd_b2 ----------------
static __global__ void hd_invD() {
    __shared__ float2 ins[32*32];
    __shared__ float2 Gs[MM*MM];    // G[p][d] for d<32
    int t = threadIdx.x;
    int bo = blockIdx.x >> 5, jc = blockIdx.x & 31;
    long base = (long)bo * 32768 + jc * 32;
    for (int i = t; i < 1024; i += 256) {
        int pd = i >> 5, jj = i & 31;
        ins[i] = hd_b3[base + (long)pd * 1024 + jj];
    }
    for (int i = t; i < MM*MM; i += 256) {
        int p = i >> 5, d = i & 31;
        Gs[i] = hd_G[p*64 + d];
    }
    __syncthreads();
    int jj = t & 31, dg = t >> 5;
    float2 ae[4], ao[4];
    #pragma unroll
    for (int k = 0; k < 4; k++) { ae[k] = make_float2(0.f,0.f); ao[k] = make_float2(0.f,0.f); }
    #pragma unroll
    for (int pd = 0; pd < 32; pd++) {
        float2 xv = ins[pd*32 + jj];
        #pragma unroll
        for (int k = 0; k < 4; k++) {
            float2 g = Gs[pd*32 + (dg + 8*k)];
            if (pd & 1) {
                ao[k].x += xv.x * g.x - xv.y * g.y;
                ao[k].y += xv.x * g.y + xv.y * g.x;
            } else {
                ae[k].x += xv.x * g.x - xv.y * g.y;
                ae[k].y += xv.x * g.y + xv.y * g.x;
            }
        }
    }
    long obase = (long)bo * 65536 + jc * 32;
    #pragma unroll
    for (int k = 0; k < 4; k++) {
        int d = dg + 8*k;
        hd_b2[obase + (long)d * 1024 + jj] =
            make_float2(ae[k].x + ao[k].x, ae[k].y + ao[k].y);
        hd_b2[obase + (long)(d + 32) * 1024 + jj] =
            make_float2(ae[k].x - ao[k].x, ae[k].y - ao[k].y);
    }
}

// ---------------- inverse H+W (radix-2): hd_b2 -> out ----------------
static __global__ void hd_invHW(float* __restrict__ outf, long fcap, int interleaved) {
    __shared__ float2 ins[32*32];
    __shared__ float2 Gs[MM*NN];
    __shared__ float2 mid[64*32];
    int t = threadIdx.x;
    long base = (long)blockIdx.x * 1024;
    for (int i = t; i < 1024; i += 256) ins[i] = hd_b2[base + i];
    for (int i = t; i < MM*NN; i += 256) Gs[i] = hd_G[i];
    __syncthreads();
    {   // H axis 32->64, radix-2 pairs (h, h+32)
        int pw = t & 31, hg = t >> 5;
        float2 ae[4], ao[4];
        #pragma unroll
        for (int k = 0; k < 4; k++) { ae[k] = make_float2(0.f,0.f); ao[k] = make_float2(0.f,0.f); }
        #pragma unroll
        for (int ph = 0; ph < 32; ph++) {
            float2 xv = ins[ph*32 + pw];
            #pragma unroll
            for (int k = 0; k < 4; k++) {
                float2 g = Gs[ph*64 + (hg + 8*k)];
                if (ph & 1) {
                    ao[k].x += xv.x * g.x - xv.y * g.y;
                    ao[k].y += xv.x * g.y + xv.y * g.x;
                } else {
                    ae[k].x += xv.x * g.x - xv.y * g.y;
                    ae[k].y += xv.x * g.y + xv.y * g.x;
                }
            }
        }
        #pragma unroll
        for (int k = 0; k < 4; k++) {
            int h = hg + 8*k;
            mid[h*32 + pw]        = make_float2(ae[k].x + ao[k].x, ae[k].y + ao[k].y);
            mid[(h + 32)*32 + pw] = make_float2(ae[k].x - ao[k].x, ae[k].y - ao[k].y);
        }
    }
    __syncthreads();
    {   // W axis 32->64, radix-2 pairs (w', w'+32)
        int w = t & 31, hg = t >> 5;    // 8 h's per thread
        float2 ae[8], ao[8];
        #pragma unroll
        for (int k = 0; k < 8; k++) { ae[k] = make_float2(0.f,0.f); ao[k] = make_float2(0.f,0.f); }
        #pragma unroll
        for (int pw = 0; pw < 32; pw++) {
            float2 g = Gs[pw*64 + w];
            #pragma unroll
            for (int k = 0; k < 8; k++) {
                float2 m = mid[(hg + 8*k)*32 + pw];
                if (pw & 1) {
                    ao[k].x += m.x * g.x - m.y * g.y;
                    ao[k].y += m.x * g.y + m.y * g.x;
                } else {
                    ae[k].x += m.x * g.x - m.y * g.y;
                    ae[k].y += m.x * g.y + m.y * g.x;
                }
            }
        }
        long obase = (long)blockIdx.x * 4096;
        if (interleaved) {
            #pragma unroll
            for (int k = 0; k < 8; k++) {
                int h = hg + 8*k;
                long f0 = (obase + h*64 + w) * 2;
                long f1 = (obase + h*64 + w + 32) * 2;
                if (f0 + 1 < fcap) { outf[f0] = ae[k].x + ao[k].x; outf[f0+1] = ae[k].y + ao[k].y; }
                if (f1 + 1 < fcap) { outf[f1] = ae[k].x - ao[k].x; outf[f1+1] = ae[k].y - ao[k].y; }
            }
        } else {
            #pragma unroll
            for (int k = 0; k < 8; k++) {
                int h = hg + 8*k;
                long f0 = obase + h*64 + w;
                long f1 = obase + h*64 + w + 32;
                if (f0 < fcap) outf[f0] = ae[k].x + ao[k].x;   // real part
                if (f1 < fcap) outf[f1] = ae[k].x - ao[k].x;
            }
        }
    }
}

extern "C" void kernel_launch(void* const* d_in, const int* in_sizes, int n_in,
                              void* d_out, int out_size) {
    const float* x  = nullptr;  long xcap = 0;
    const float* Wsmall[2] = {nullptr, nullptr};
    long wcap = 0;
    int nsmall = 0;
    for (int i = 0; i < n_in; i++) {
        if (in_sizes[i] > 1000000) {
            x = (const float*)d_in[i];
            xcap = (long)in_sizes[i];
        } else if (nsmall < 2) {
            if (nsmall == 0) wcap = (long)in_sizes[i];
            Wsmall[nsmall++] = (const float*)d_in[i];
        }
    }
    if (!x || nsmall < 2) return;
    const float* Wr = Wsmall[0];
    const float* Wi = Wsmall[1];

    long S = (long)out_size;
    long fcap;
    int  interleaved;
    if (S >= 200000000)      { fcap = S / 4; interleaved = 1; }
    else if (S >= 100000000) { fcap = S / 4; interleaved = 0; }
    else if (S >= 50000000)  { fcap = S;     interleaved = 1; }
    else                     { fcap = S;     interleaved = 0; }
    float* outf = (float*)d_out;

    hd_tables<<<1, 256>>>();
    hd_basis<<<VV/256, 256>>>();
    hd_blkcnt<<<NBLK, 256>>>();
    hd_scan<<<1, 32>>>();
    hd_scatter<<<NBLK, 256>>>();
    hd_perm<<<NBLK, 256>>>();

    hd_f12<<<BATCH*CI*NN, 256>>>(x, xcap);    // 8192 blocks
    hd_s3f<<<BATCH*CI*32, 256>>>();           // 4096

    hd_proj<<<BATCH*CI*NSH, 256>>>();         // 2048
    hd_mix<<<(BATCH*CO*NSH*NL + 255)/256, 256>>>(Wr, Wi, wcap);
    hd_recon<<<BATCH*CO*128, 256>>>();        // 16384

    hd_invD<<<BATCH*CO*32, 256>>>();          // 4096
    hd_invHW<<<BATCH*CO*NN, 256>>>(outf, fcap, interleaved);   // 8192
}

// round 17
// speedup vs baseline: 1.7100x; 1.0818x over previous
#include <cuda_runtime.h>

#define BATCH 4
#define CI    32
#define CO    32
#define NN    64
#define MM    32
#define VV    32768      // 32^3
#define NSH   16
#define NL    9
#define NBLK  128        // VV/256 voxel blocks for the sort

// -------- static scratch --------
static __device__ float2 hd_b2[BATCH*CI*NN*MM*MM];   // 67 MB  [bc*64+d][1024]
static __device__ float2 hd_b3[BATCH*CI*MM*MM*MM];   // 33 MB  Xb (fwd only)
static __device__ float2 hd_coef[BATCH*CI*NSH*NL];
static __device__ float2 hd_mixg[BATCH*CO*NSH*NL];
static __device__ float2 hd_F[NN*MM];                // F[n][p] = e^{-i pi (p-16) n / 32}
static __device__ float2 hd_G[MM*NN];                // G[p][n] = e^{+i pi (p-16) n / 32} / 64
static __device__ float  hd_Y[NL*VV];
static __device__ int    hd_sh[VV];
// sort structures
static __device__ int    hd_bcnt[NBLK*NSH];
static __device__ int    hd_boff[NBLK*NSH];
static __device__ int    hd_shoff[NSH+1];
static __device__ int    hd_vidx[VV];
static __device__ float  hd_Ys[NL*VV];               // Y in shell-sorted order

// ---------------- init: twiddles (16 blocks) ----------------
static __global__ void hd_tables() {
    int i = blockIdx.x * 256 + threadIdx.x;   // grid 16*256 = 4096 >= 2048+2048
    if (i < NN*MM) {
        int n = i / MM, p = i % MM;
        float a = -(float)((p - 16) * n) / 32.0f;
        float s, c; sincospif(a, &s, &c);
        hd_F[i] = make_float2(c, s);
    }
    int j = i - NN*MM;
    if (j >= 0 && j < MM*NN) {
        int p = j / NN, n = j % NN;
        float a = (float)((p - 16) * n) / 32.0f;
        float s, c; sincospif(a, &s, &c);
        hd_G[j] = make_float2(c * (1.0f/64.0f), s * (1.0f/64.0f));
    }
}

// ---------------- init: shell + SH basis ----------------
static __global__ void hd_basis() {
    int v = blockIdx.x * blockDim.x + threadIdx.x;
    if (v >= VV) return;
    int p = v >> 10, q = (v >> 5) & 31, w = v & 31;
    int kx = p - 16, ky = q - 16, kz = w - 16;
    int q2 = kx*kx + ky*ky + kz*kz;
    float Yv[NL];
    int shell;
    if (q2 == 0) {
        Yv[0] = 0.282095f;
        #pragma unroll
        for (int l = 1; l < NL; l++) Yv[l] = 0.0f;
        shell = 0;
    } else {
        float r    = __fsqrt_rn((float)q2);
        float rmax = __fsqrt_rn(768.0f);
        float ux = __fdiv_rn((float)kx, r);
        float uy = __fdiv_rn((float)ky, r);
        float uz = __fdiv_rn((float)kz, r);
        Yv[0] = 0.282095f;
        Yv[1] = 0.488603f * uy;
        Yv[2] = 0.488603f * uz;
        Yv[3] = 0.488603f * ux;
        Yv[4] = 1.092548f * ux * uy;
        Yv[5] = 1.092548f * uy * uz;
        Yv[6] = 0.315392f * (3.0f * uz * uz - 1.0f);
        Yv[7] = 1.092548f * ux * uz;
        Yv[8] = 0.546274f * (ux * ux - uy * uy);
        float val = __fmul_rn(__fdiv_rn(r, rmax), 16.0f);
        shell = (int)val; if (shell > 15) shell = 15;
    }
    hd_sh[v] = shell;
    #pragma unroll
    for (int l = 0; l < NL; l++) hd_Y[l*VV + v] = Yv[l];
}

// ---------------- sort: per-block shell counts ----------------
static __global__ void hd_blkcnt() {        // grid NBLK, block 256
    __shared__ int cnt[NSH];
    int t = threadIdx.x;
    if (t < NSH) cnt[t] = 0;
    __syncthreads();
    atomicAdd(&cnt[hd_sh[blockIdx.x*256 + t]], 1);
    __syncthreads();
    if (t < NSH) hd_bcnt[blockIdx.x*NSH + t] = cnt[t];
}

// ---------------- sort: offsets (1 block, 512 threads = 16 warps) ----------------
static __global__ void hd_scan() {
    __shared__ int tot[NSH];
    int wid = threadIdx.x >> 5, lane = threadIdx.x & 31;   // warp wid handles shell wid
    // 1. per-shell totals
    int c = 0;
    for (int b = lane; b < NBLK; b += 32) c += hd_bcnt[b*NSH + wid];
    #pragma unroll
    for (int o = 16; o > 0; o >>= 1) c += __shfl_down_sync(0xffffffffu, c, o);
    if (lane == 0) tot[wid] = c;
    __syncthreads();
    // 2. shell prefix
    if (threadIdx.x == 0) {
        int run = 0;
        #pragma unroll
        for (int i = 0; i < NSH; i++) { hd_shoff[i] = run; run += tot[i]; }
        hd_shoff[NSH] = run;
    }
    __syncthreads();
    // 3. per-block offsets: warp-scan over 128 blocks in 4 chunks of 32
    int run = hd_shoff[wid];
    for (int c0 = 0; c0 < NBLK; c0 += 32) {
        int v = hd_bcnt[(c0 + lane)*NSH + wid];
        int incl = v;
        #pragma unroll
        for (int o = 1; o < 32; o <<= 1) {
            int u = __shfl_up_sync(0xffffffffu, incl, o);
            if (lane >= o) incl += u;
        }
        hd_boff[(c0 + lane)*NSH + wid] = run + incl - v;
        run += __shfl_sync(0xffffffffu, incl, 31);
    }
}

// ---------------- sort: deterministic scatter ----------------
static __global__ void hd_scatter() {       // grid NBLK, block 256
    __shared__ int pos[256];
    int t = threadIdx.x;
    int v0 = blockIdx.x * 256;
    if (t == 0) {
        int local[NSH];
        #pragma unroll
        for (int s = 0; s < NSH; s++) local[s] = hd_boff[blockIdx.x*NSH + s];
        for (int i = 0; i < 256; i++) { int s = hd_sh[v0 + i]; pos[i] = local[s]++; }
    }
    __syncthreads();
    hd_vidx[pos[t]] = v0 + t;
}

// ---------------- sort: permute Y into shell order ----------------
static __global__ void hd_perm() {          // grid NBLK, block 256
    int j = blockIdx.x * 256 + threadIdx.x;
    int v = hd_vidx[j];
    #pragma unroll
    for (int l = 0; l < NL; l++) hd_Ys[l*VV + j] = hd_Y[l*VV + v];
}

// ---------------- forward W+H (radix-2): block per (b,c,d) slab ----------------
static __global__ void hd_f12(const float* __restrict__ x, long xcap) {
    __shared__ float  xs[64*64];
    __shared__ float2 mid[64*32];
    int t = threadIdx.x;
    long base = (long)blockIdx.x * 4096;
    for (int i = t; i < 4096; i += 256) {
        long gi = base + i;
        xs[i] = (gi < xcap) ? x[gi] : 0.0f;
    }
    __syncthreads();
    // butterfly W
    for (int i = t; i < 2048; i += 256) {
        int h = i >> 5, w = i & 31;
        float a = xs[h*64 + w], b = xs[h*64 + w + 32];
        xs[h*64 + w] = a + b;
        xs[h*64 + w + 32] = a - b;
    }
    __syncthreads();
    {   // stage A (W axis, 32-term), float2 smem loads (w unrolled x2)
        int pw = t & 31, hg = t >> 5;
        int off = (pw & 1) ? 32 : 0;
        float2 acc[8];
        #pragma unroll
        for (int k = 0; k < 8; k++) acc[k] = make_float2(0.f, 0.f);
        #pragma unroll 4
        for (int w2 = 0; w2 < 16; w2++) {
            float2 f0 = hd_F[(2*w2)*32 + pw];
            float2 f1 = hd_F[(2*w2 + 1)*32 + pw];
            #pragma unroll
            for (int k = 0; k < 8; k++) {
                float2 xv = *reinterpret_cast<const float2*>(
                    &xs[(hg + 8*k)*64 + off + 2*w2]);
                acc[k].x += xv.x * f0.x + xv.y * f1.x;
                acc[k].y += xv.x * f0.y + xv.y * f1.y;
            }
        }
        #pragma unroll
        for (int k = 0; k < 8; k++) mid[(hg + 8*k)*32 + pw] = acc[k];
    }
    __syncthreads();
    // butterfly H on mid (complex)
    for (int i = t; i < 1024; i += 256) {
        int h = i >> 5, pw = i & 31;
        float2 a = mid[h*32 + pw], b = mid[(h + 32)*32 + pw];
        mid[h*32 + pw]        = make_float2(a.x + b.x, a.y + b.y);
        mid[(h + 32)*32 + pw] = make_float2(a.x - b.x, a.y - b.y);
    }
    __syncthreads();
    {   // stage B (H axis, 32-term)
        int pw = t & 31, pg = t >> 5;
        int off = (pg & 1) ? 32 : 0;
        float2 acc[4];
        #pragma unroll
        for (int k = 0; k < 4; k++) acc[k] = make_float2(0.f, 0.f);
        #pragma unroll 4
        for (int h = 0; h < 32; h++) {
            float2 m = mid[(off + h)*32 + pw];
            #pragma unroll
            for (int k = 0; k < 4; k++) {
                float2 f = hd_F[h*32 + (pg + 8*k)];
                acc[k].x += m.x * f.x - m.y * f.y;
                acc[k].y += m.x * f.y + m.y * f.x;
            }
        }
        long obase = (long)blockIdx.x * 1024;
        #pragma unroll
        for (int k = 0; k < 4; k++)
            hd_b2[obase + (pg + 8*k)*32 + pw] = acc[k];
    }
}

// ---------------- forward D (radix-2): hd_b2 -> hd_b3 ----------------
static __global__ void hd_s3f() {
    __shared__ float2 ins[64*32];
    __shared__ float2 Fs[MM*MM];
    int t = threadIdx.x;
    int bc = blockIdx.x >> 5, jc = blockIdx.x & 31;
    long base = (long)bc * 65536 + jc * 32;
    for (int i = t; i < 2048; i += 256) {
        int d = i >> 5, jj = i & 31;
        ins[i] = hd_b2[base + (long)d * 1024 + jj];
    }
    for (int i = t; i < MM*MM; i += 256) Fs[i] = hd_F[i];
    __syncthreads();
    for (int i = t; i < 1024; i += 256) {
        int d = i >> 5, jj = i & 31;
        float2 a = ins[d*32 + jj], b = ins[(d + 32)*32 + jj];
        ins[d*32 + jj]        = make_float2(a.x + b.x, a.y + b.y);
        ins[(d + 32)*32 + jj] = make_float2(a.x - b.x, a.y - b.y);
    }
    __syncthreads();
    int jj = t & 31, pg = t >> 5;
    int off = (pg & 1) ? 32 : 0;
    float2 acc[4];
    #pragma unroll
    for (int k = 0; k < 4; k++) acc[k] = make_float2(0.f, 0.f);
    #pragma unroll 4
    for (int d = 0; d < 32; d++) {
        float2 xv = ins[(off + d)*32 + jj];
        #pragma unroll
        for (int k = 0; k < 4; k++) {
            float2 f = Fs[d*32 + (pg + 8*k)];
            acc[k].x += xv.x * f.x - xv.y * f.y;
            acc[k].y += xv.x * f.y + xv.y * f.x;
        }
    }
    long obase = (long)bc * 32768 + jc * 32;
    #pragma unroll
    for (int k = 0; k < 4; k++)
        hd_b3[obase + (long)(pg + 8*k) * 1024 + jj] = acc[k];
}

// ---------------- projection (shell-sorted) ----------------
static __global__ void hd_proj() {
    int bi = blockIdx.x >> 4, s = blockIdx.x & 15;
    int t = threadIdx.x;
    int st = hd_shoff[s], en = hd_shoff[s+1];
    long base = (long)bi * VV;
    float2 acc[NL];
    #pragma unroll
    for (int l = 0; l < NL; l++) acc[l] = make_float2(0.f, 0.f);
    for (int j = st + t; j < en; j += 256) {
        int v = hd_vidx[j];
        float2 X = hd_b3[base + v];
        #pragma unroll
        for (int l = 0; l < NL; l++) {
            float y = hd_Ys[l*VV + j];
            acc[l].x += y * X.x;
            acc[l].y += y * X.y;
        }
    }
    __shared__ float2 red[256];
    int n = en - st; if (n < 1) n = 1;
    float inv = 1.0f / (float)n;
    for (int l = 0; l < NL; l++) {
        red[t] = acc[l];
        __syncthreads();
        for (int off = 128; off > 0; off >>= 1) {
            if (t < off) { red[t].x += red[t+off].x; red[t].y += red[t+off].y; }
            __syncthreads();
        }
        if (t == 0)
            hd_coef[(bi*NSH + s)*NL + l] = make_float2(red[0].x * inv, red[0].y * inv);
        __syncthreads();
    }
}

// ---------------- channel mix ----------------
static __global__ void hd_mix(const float* __restrict__ Wr,
                              const float* __restrict__ Wi, long wcap) {
    int gid = blockIdx.x * blockDim.x + threadIdx.x;
    if (gid >= BATCH*CO*NSH*NL) return;
    int l = gid % NL;
    int s = (gid / NL) % NSH;
    int o = (gid / (NL*NSH)) % CO;
    int b = gid / (NL*NSH*CO);
    float ar = 0.f, ai = 0.f;
    for (int i = 0; i < CI; i++) {
        float2 c = hd_coef[((b*CI + i)*NSH + s)*NL + l];
        long wi = ((long)(i*CO + o)*NSH + s)*NL + l;
        float wr  = (wi < wcap) ? Wr[wi] : 0.0f;
        float wim = (wi < wcap) ? Wi[wi] : 0.0f;
        ar += c.x * wr - c.y * wim;
        ai += c.x * wim + c.y * wr;
    }
    hd_mixg[gid] = make_float2(ar, ai);
}

// ---------------- fused recon + inverse D (32->64): hd_mixg -> hd_b2 ----------
static __global__ void hd_invD() {
    __shared__ float2 ins[32*32];
    __shared__ float2 Gs[MM*MM];    // G[p][d] for d<32
    __shared__ float2 mix_s[NSH*NL];
    int t = threadIdx.x;
    int bo = blockIdx.x >> 5, jc = blockIdx.x & 31;
    if (t < NSH*NL) mix_s[t] = hd_mixg[bo*NSH*NL + t];
    for (int i = t; i < MM*MM; i += 256) {
        int p = i >> 5, d = i & 31;
        Gs[i] = hd_G[p*64 + d];
    }
    __syncthreads();
    // reconstruct Xrec for this block's 1024 voxels (fused hd_recon)
    for (int i = t; i < 1024; i += 256) {
        int pd = i >> 5, jj = i & 31;
        int v = pd*1024 + jc*32 + jj;
        int s = hd_sh[v];
        float ar = 0.f, ai = 0.f;
        #pragma unroll
        for (int l = 0; l < NL; l++) {
            float y = hd_Y[l*VV + v];
            float2 m = mix_s[s*NL + l];
            ar += y * m.x;
            ai += y * m.y;
        }
        ins[i] = make_float2(ar, ai);
    }
    __syncthreads();
    int jj = t & 31, dg = t >> 5;
    float2 ae[4], ao[4];
    #pragma unroll
    for (int k = 0; k < 4; k++) { ae[k] = make_float2(0.f,0.f); ao[k] = make_float2(0.f,0.f); }
    #pragma unroll
    for (int pd = 0; pd < 32; pd++) {
        float2 xv = ins[pd*32 + jj];
        #pragma unroll
        for (int k = 0; k < 4; k++) {
            float2 g = Gs[pd*32 + (dg + 8*k)];
            if (pd & 1) {
                ao[k].x += xv.x * g.x - xv.y * g.y;
                ao[k].y += xv.x * g.y + xv.y * g.x;
            } else {
                ae[k].x += xv.x * g.x - xv.y * g.y;
                ae[k].y += xv.x * g.y + xv.y * g.x;
            }
        }
    }
    long obase = (long)bo * 65536 + jc * 32;
    #pragma unroll
    for (int k = 0; k < 4; k++) {
        int d = dg + 8*k;
        hd_b2[obase + (long)d * 1024 + jj] =
            make_float2(ae[k].x + ao[k].x, ae[k].y + ao[k].y);
        hd_b2[obase + (long)(d + 32) * 1024 + jj] =
            make_float2(ae[k].x - ao[k].x, ae[k].y - ao[k].y);
    }
}

// ---------------- inverse H+W (radix-2): hd_b2 -> out ----------------
static __global__ void hd_invHW(float* __restrict__ outf, long fcap, int interleaved) {
    __shared__ float2 ins[32*32];
    __shared__ float2 Gs[MM*NN];
    __shared__ float2 mid[64*32];
    int t = threadIdx.x;
    long base = (long)blockIdx.x * 1024;
    for (int i = t; i < 1024; i += 256) ins[i] = hd_b2[base + i];
    for (int i = t; i < MM*NN; i += 256) Gs[i] = hd_G[i];
    __syncthreads();
    {   // H axis 32->64, radix-2 pairs (h, h+32)
        int pw = t & 31, hg = t >> 5;
        float2 ae[4], ao[4];
        #pragma unroll
        for (int k = 0; k < 4; k++) { ae[k] = make_float2(0.f,0.f); ao[k] = make_float2(0.f,0.f); }
        #pragma unroll
        for (int ph = 0; ph < 32; ph++) {
            float2 xv = ins[ph*32 + pw];
            #pragma unroll
            for (int k = 0; k < 4; k++) {
                float2 g = Gs[ph*64 + (hg + 8*k)];
                if (ph & 1) {
                    ao[k].x += xv.x * g.x - xv.y * g.y;
                    ao[k].y += xv.x * g.y + xv.y * g.x;
                } else {
                    ae[k].x += xv.x * g.x - xv.y * g.y;
                    ae[k].y += xv.x * g.y + xv.y * g.x;
                }
            }
        }
        #pragma unroll
        for (int k = 0; k < 4; k++) {
            int h = hg + 8*k;
            mid[h*32 + pw]        = make_float2(ae[k].x + ao[k].x, ae[k].y + ao[k].y);
            mid[(h + 32)*32 + pw] = make_float2(ae[k].x - ao[k].x, ae[k].y - ao[k].y);
        }
    }
    __syncthreads();
    long obase = (long)blockIdx.x * 4096;
    if (interleaved) {
        // W axis 32->64, complex output
        int w = t & 31, hg = t >> 5;
        float2 ae[8], ao[8];
        #pragma unroll
        for (int k = 0; k < 8; k++) { ae[k] = make_float2(0.f,0.f); ao[k] = make_float2(0.f,0.f); }
        #pragma unroll
        for (int pw = 0; pw < 32; pw++) {
            float2 g = Gs[pw*64 + w];
            #pragma unroll
            for (int k = 0; k < 8; k++) {
                float2 m = mid[(hg + 8*k)*32 + pw];
                if (pw & 1) {
                    ao[k].x += m.x * g.x - m.y * g.y;
                    ao[k].y += m.x * g.y + m.y * g.x;
                } else {
                    ae[k].x += m.x * g.x - m.y * g.y;
                    ae[k].y += m.x * g.y + m.y * g.x;
                }
            }
        }
        #pragma unroll
        for (int k = 0; k < 8; k++) {
            int h = hg + 8*k;
            long f0 = (obase + h*64 + w) * 2;
            long f1 = (obase + h*64 + w + 32) * 2;
            if (f0 + 1 < fcap) { outf[f0] = ae[k].x + ao[k].x; outf[f0+1] = ae[k].y + ao[k].y; }
            if (f1 + 1 < fcap) { outf[f1] = ae[k].x - ao[k].x; outf[f1+1] = ae[k].y - ao[k].y; }
        }
    } else {
        // W axis 32->64, REAL part only (imag accumulation skipped entirely)
        int w = t & 31, hg = t >> 5;
        float ae[8], ao[8];
        #pragma unroll
        for (int k = 0; k < 8; k++) { ae[k] = 0.f; ao[k] = 0.f; }
        #pragma unroll
        for (int pw = 0; pw < 32; pw++) {
            float2 g = Gs[pw*64 + w];
            #pragma unroll
            for (int k = 0; k < 8; k++) {
                float2 m = mid[(hg + 8*k)*32 + pw];
                if (pw & 1) ao[k] += m.x * g.x - m.y * g.y;
                else        ae[k] += m.x * g.x - m.y * g.y;
            }
        }
        #pragma unroll
        for (int k = 0; k < 8; k++) {
            int h = hg + 8*k;
            long f0 = obase + h*64 + w;
            long f1 = obase + h*64 + w + 32;
            if (f0 < fcap) outf[f0] = ae[k] + ao[k];
            if (f1 < fcap) outf[f1] = ae[k] - ao[k];
        }
    }
}

extern "C" void kernel_launch(void* const* d_in, const int* in_sizes, int n_in,
                              void* d_out, int out_size) {
    const float* x  = nullptr;  long xcap = 0;
    const float* Wsmall[2] = {nullptr, nullptr};
    long wcap = 0;
    int nsmall = 0;
    for (int i = 0; i < n_in; i++) {
        if (in_sizes[i] > 1000000) {
            x = (const float*)d_in[i];
            xcap = (long)in_sizes[i];
        } else if (nsmall < 2) {
            if (nsmall == 0) wcap = (long)in_sizes[i];
            Wsmall[nsmall++] = (const float*)d_in[i];
        }
    }
    if (!x || nsmall < 2) return;
    const float* Wr = Wsmall[0];
    const float* Wi = Wsmall[1];

    long S = (long)out_size;
    long fcap;
    int  interleaved;
    if (S >= 200000000)      { fcap = S / 4; interleaved = 1; }
    else if (S >= 100000000) { fcap = S / 4; interleaved = 0; }
    else if (S >= 50000000)  { fcap = S;     interleaved = 1; }
    else                     { fcap = S;     interleaved = 0; }
    float* outf = (float*)d_out;

    hd_tables<<<16, 256>>>();
    hd_basis<<<VV/256, 256>>>();
    hd_blkcnt<<<NBLK, 256>>>();
    hd_scan<<<1, 512>>>();
    hd_scatter<<<NBLK, 256>>>();
    hd_perm<<<NBLK, 256>>>();

    hd_f12<<<BATCH*CI*NN, 256>>>(x, xcap);    // 8192 blocks
    hd_s3f<<<BATCH*CI*32, 256>>>();           // 4096

    hd_proj<<<BATCH*CI*NSH, 256>>>();         // 2048
    hd_mix<<<(BATCH*CO*NSH*NL + 255)/256, 256>>>(Wr, Wi, wcap);

    hd_invD<<<BATCH*CO*32, 256>>>();          // 4096 (recon fused)
    hd_invHW<<<BATCH*CO*NN, 256>>>(outf, fcap, interleaved);   // 8192
}